// round 16
// baseline (speedup 1.0000x reference)
#include <cuda_runtime.h>

#define NB     2048
#define NOH    20
#define NOTH   23
#define NC     10
#define SC     200      // NOH*NC
#define EMB    9
#define OUTC   32
#define XSTR   43       // NOH + NOTH
#define HW     2304     // 48*48
#define SLABSZ 73728    // OUTC*HW floats per batch

#define THREADS 512

// Single fused kernel, R10 structure with one change: 2 CTAs/SM instead of 1
// (grid 18 x 8 x 2 = 288 CTAs x 512 threads). Each CTA handles 128 of the 256
// batches of its (mtile, c) tile -> two independent preamble/store streams
// per SM (preamble latency hiding + more DRAM address streams).
//
// Verified identities (rel_err ~1.4e-7, R1-R15):
//   out[b][o][m] depends on b only through c = b & 7
//   three 1x1 convs fold into one 32x32 weight W + bias cb
//   slab[c][o][m] = cb[o] + sum_i W[o,i]  * v[256*((c+i)&7)+q, r]  (q=m/9, r=m%9)
//                         + sum_j W[o,9+j]* x[bb_j*43+20+(4j+m)%23],
//                           bb_j = (256c + (2304j+m)/23) & 2047
__global__ void __launch_bounds__(THREADS, 2) k_all(
    const float* __restrict__ x,
    const float* __restrict__ fc_w, const float* __restrict__ fc_b,
    const float* __restrict__ oh_w, const float* __restrict__ oh_b,
    const float* __restrict__ ot_w, const float* __restrict__ ot_b,
    const float* __restrict__ all_w, const float* __restrict__ all_b,
    float* __restrict__ out)
{
    __shared__ __align__(16) float s_fcw[EMB * SC];    // 7.2 KB
    __shared__ __align__(16) float s_W[OUTC * 32];     // fused weight
    __shared__ float s_cb[OUTC];                       // fused bias
    __shared__ float s_v[8][16][EMB];                  // embedding rows this tile needs
    __shared__ __align__(16) float s_out[OUTC * 128];  // 16 KB tile [o][m_local]

    const int t     = threadIdx.x;       // 0..511
    const int mtile = blockIdx.x;        // 0..17
    const int c     = blockIdx.y;        // 0..7
    const int bs    = blockIdx.z;        // 0..1 : batch half

    // ---- stage fc_w (coalesced) --------------------------------------------
    for (int i = t; i < EMB * SC; i += THREADS) s_fcw[i] = fc_w[i];

    // ---- fold the three convs into one 32x32 weight + bias (2 entries/thr) -
    #pragma unroll
    for (int k = 0; k < 2; k++) {
        int idx = t + THREADS * k;       // 0..1023
        int o = idx >> 5, i = idx & 31;
        float s = 0.f;
        if (i < EMB) {
            #pragma unroll
            for (int cc = 0; cc < EMB; cc++)
                s += all_w[o * 32 + cc] * oh_w[cc * EMB + i];
        } else {
            int j = i - EMB;
            #pragma unroll
            for (int cc = 0; cc < NOTH; cc++)
                s += all_w[o * 32 + EMB + cc] * ot_w[cc * NOTH + j];
        }
        s_W[idx] = s;
    }
    if (t < OUTC) {
        float cb = all_b[t];
        #pragma unroll
        for (int cc = 0; cc < EMB; cc++)  cb += all_w[t * 32 + cc] * oh_b[cc];
        #pragma unroll
        for (int cc = 0; cc < NOTH; cc++) cb += all_w[t * 32 + EMB + cc] * ot_b[cc];
        s_cb[t] = cb;
    }
    __syncthreads();    // s_fcw ready

    // ---- embedding rows needed by this m-tile (<=128 rows, 1 per thread) ---
    const int m0 = mtile * 128;
    const int q0 = m0 / 9;
    const int nq = (m0 + 127) / 9 - q0 + 1;   // <= 16

    if (t < 8 * nq) {
        int k  = t / nq;
        int ql = t - k * nq;
        int b  = 256 * k + q0 + ql;
        const float* xr = x + b * XSTR;       // 20 consecutive floats (~3 lines)
        float acc[EMB];
        #pragma unroll
        for (int e = 0; e < EMB; e++) acc[e] = fc_b[e];
        #pragma unroll
        for (int j = 0; j < NOH; j++) {
            int id   = (int)xr[j];
            int base = j * NC + id;
            #pragma unroll
            for (int e = 0; e < EMB; e++) acc[e] += s_fcw[e * SC + base];
        }
        #pragma unroll
        for (int e = 0; e < EMB; e++) s_v[k][ql][e] = acc[e];
    }
    __syncthreads();    // s_W, s_cb, s_v ready

    // ---- compute tile: thread -> (m_local = t&127, 8 channels) -------------
    {
        const int ml = t & 127;
        const int o0 = (t >> 7) * 8;          // 4 groups of 8 channels
        const int m  = m0 + ml;
        const int q  = m / 9;
        const int r  = m - 9 * q;
        const int ql = q - q0;

        float g[32];
        #pragma unroll
        for (int i = 0; i < 9; i++)
            g[i] = s_v[(c + i) & 7][ql][r];
        #pragma unroll
        for (int j = 0; j < 23; j++) {
            int eo = (4 * j + m) % 23;
            int T  = (2304 * j + m) / 23;
            int bb = (256 * c + T) & 2047;
            g[9 + j] = x[bb * XSTR + NOH + eo];
        }

        #pragma unroll
        for (int chn = 0; chn < 8; chn++) {
            int o = o0 + chn;
            const float4* W4 = (const float4*)(s_W + o * 32);
            float s = s_cb[o];
            #pragma unroll
            for (int j4 = 0; j4 < 8; j4++) {
                float4 w = W4[j4];
                s += w.x * g[4 * j4]     + w.y * g[4 * j4 + 1]
                   + w.z * g[4 * j4 + 2] + w.w * g[4 * j4 + 3];
            }
            s_out[o * 128 + ml] = s;
        }
    }
    __syncthreads();    // tile ready (4096 floats = 1024 float4)

    // ---- store phase: each thread owns TWO float4, 128 batches -------------
    const float4 r0 = ((const float4*)s_out)[t];
    const float4 r1 = ((const float4*)s_out)[t + 512];

    // float4 index f -> o = f>>5, ml4 = f&31
    const size_t off0 = (size_t)((t      ) >> 5) * (HW / 4) + ((t      ) & 31);
    const size_t off1 = (size_t)((t + 512) >> 5) * (HW / 4) + ((t + 512) & 31);

    float4* __restrict__ base = (float4*)out
        + (size_t)c * (SLABSZ / 4)            // batch residue component
        + (size_t)(m0 >> 2);                  // spatial

    // stagger batch order per CTA to decorrelate chip-wide write windows
    const int cta   = mtile + 18 * (c + 8 * bs);  // 0..287
    const int start = (cta * 37) & 127;

    #pragma unroll 4
    for (int vv = 0; vv < 128; vv++) {
        int u = bs * 128 + ((vv + start) & 127);  // b = c + 8u
        float4* __restrict__ dst = base + (size_t)u * (8 * SLABSZ / 4);
        dst[off0] = r0;
        dst[off1] = r1;
    }
}

// ---------------------------------------------------------------------------
extern "C" void kernel_launch(void* const* d_in, const int* in_sizes, int n_in,
                              void* d_out, int out_size) {
    const float* x     = (const float*)d_in[0];
    const float* fc_w  = (const float*)d_in[1];
    const float* fc_b  = (const float*)d_in[2];
    const float* oh_w  = (const float*)d_in[3];
    const float* oh_b  = (const float*)d_in[4];
    const float* ot_w  = (const float*)d_in[5];
    const float* ot_b  = (const float*)d_in[6];
    const float* all_w = (const float*)d_in[7];
    const float* all_b = (const float*)d_in[8];
    float* out = (float*)d_out;

    dim3 grid(18, 8, 2);   // 288 CTAs, 2 CTAs/SM, single wave
    k_all<<<grid, THREADS>>>(x, fc_w, fc_b, oh_w, oh_b, ot_w, ot_b,
                             all_w, all_b, out);
}

// round 17
// speedup vs baseline: 1.0381x; 1.0381x over previous
#include <cuda_runtime.h>

#define NB     2048
#define NOH    20
#define NOTH   23
#define NC     10
#define SC     200      // NOH*NC
#define EMB    9
#define OUTC   32
#define XSTR   43       // NOH + NOTH
#define HW     2304     // 48*48
#define SLABSZ 73728    // OUTC*HW floats per batch

#define THREADS 1024

// Single fused, single-wave kernel — R10 structure (best: 104.7us) with a
// leaner preamble: v-row gathers read fc_w directly from L2 (no smem staging,
// issued at cycle 0), weight-fold FMA overlaps their latency, one fewer
// __syncthreads. Store phase byte-identical to R10.
//
// Verified identities (rel_err ~1.4e-7, R1-R16):
//   out[b][o][m] depends on b only through c = b & 7
//   three 1x1 convs fold into one 32x32 weight W + bias cb
//   slab[c][o][m] = cb[o] + sum_i W[o,i]  * v[256*((c+i)&7)+q, r]  (q=m/9, r=m%9)
//                         + sum_j W[o,9+j]* x[bb_j*43+20+(4j+m)%23],
//                           bb_j = (256c + (2304j+m)/23) & 2047
__global__ void __launch_bounds__(THREADS, 1) k_all(
    const float* __restrict__ x,
    const float* __restrict__ fc_w, const float* __restrict__ fc_b,
    const float* __restrict__ oh_w, const float* __restrict__ oh_b,
    const float* __restrict__ ot_w, const float* __restrict__ ot_b,
    const float* __restrict__ all_w, const float* __restrict__ all_b,
    float* __restrict__ out)
{
    __shared__ __align__(16) float s_W[OUTC * 32];     // fused weight
    __shared__ float s_cb[OUTC];                       // fused bias
    __shared__ float s_v[8][16][EMB];                  // embedding rows this tile needs
    __shared__ __align__(16) float s_out[OUTC * 128];  // 16 KB tile [o][m_local]

    const int t     = threadIdx.x;       // 0..1023
    const int mtile = blockIdx.x;        // 0..17
    const int c     = blockIdx.y;        // 0..7

    const int m0 = mtile * 128;
    const int q0 = m0 / 9;
    const int nq = (m0 + 127) / 9 - q0 + 1;   // <= 16

    // ---- phase A: v-rows this tile needs, straight from gmem/L2 ------------
    // Issued first so the long-latency x / fc_w gathers overlap phase B's FMA.
    if (t < 8 * nq) {
        int k  = t / nq;
        int ql = t - k * nq;
        int b  = 256 * k + q0 + ql;
        const float* xr = x + b * XSTR;       // 20 consecutive floats (~3 lines)
        float acc[EMB];
        #pragma unroll
        for (int e = 0; e < EMB; e++) acc[e] = fc_b[e];
        #pragma unroll
        for (int j = 0; j < NOH; j++) {
            int id   = (int)xr[j];
            int base = j * NC + id;
            #pragma unroll
            for (int e = 0; e < EMB; e++) acc[e] += fc_w[e * SC + base];
        }
        #pragma unroll
        for (int e = 0; e < EMB; e++) s_v[k][ql][e] = acc[e];
    }

    // ---- phase B: fold the three convs into one 32x32 weight + bias --------
    {
        int o = t >> 5, i = t & 31;
        float s = 0.f;
        if (i < EMB) {
            #pragma unroll
            for (int cc = 0; cc < EMB; cc++)
                s += all_w[o * 32 + cc] * oh_w[cc * EMB + i];
        } else {
            int j = i - EMB;
            #pragma unroll
            for (int cc = 0; cc < NOTH; cc++)
                s += all_w[o * 32 + EMB + cc] * ot_w[cc * NOTH + j];
        }
        s_W[t] = s;
    }
    if (t < OUTC) {
        float cb = all_b[t];
        #pragma unroll
        for (int cc = 0; cc < EMB; cc++)  cb += all_w[t * 32 + cc] * oh_b[cc];
        #pragma unroll
        for (int cc = 0; cc < NOTH; cc++) cb += all_w[t * 32 + EMB + cc] * ot_b[cc];
        s_cb[t] = cb;
    }
    __syncthreads();    // s_W, s_cb, s_v all ready (single preamble sync)

    // ---- compute tile: thread -> (m_local = t&127, 4 channels) -------------
    {
        const int ml = t & 127;
        const int o0 = (t >> 7) * 4;          // 8 groups of 4 channels
        const int m  = m0 + ml;
        const int q  = m / 9;
        const int r  = m - 9 * q;
        const int ql = q - q0;

        float g[32];
        #pragma unroll
        for (int i = 0; i < 9; i++)
            g[i] = s_v[(c + i) & 7][ql][r];
        #pragma unroll
        for (int j = 0; j < 23; j++) {
            int eo = (4 * j + m) % 23;
            int T  = (2304 * j + m) / 23;
            int bb = (256 * c + T) & 2047;
            g[9 + j] = x[bb * XSTR + NOH + eo];
        }

        #pragma unroll
        for (int chn = 0; chn < 4; chn++) {
            int o = o0 + chn;
            const float4* W4 = (const float4*)(s_W + o * 32);
            float s = s_cb[o];
            #pragma unroll
            for (int j4 = 0; j4 < 8; j4++) {
                float4 w = W4[j4];
                s += w.x * g[4 * j4]     + w.y * g[4 * j4 + 1]
                   + w.z * g[4 * j4 + 2] + w.w * g[4 * j4 + 3];
            }
            s_out[o * 128 + ml] = s;
        }
    }
    __syncthreads();    // tile ready (4096 floats = 1024 float4)

    // ---- store phase: each thread owns exactly ONE float4 (R10-identical) --
    const float4 r0 = ((const float4*)s_out)[t];
    const int o   = t >> 5;
    const int ml4 = t & 31;

    float4* __restrict__ base = (float4*)out
        + (size_t)c * (SLABSZ / 4)            // batch residue component
        + (size_t)o * (HW / 4)                // channel
        + (size_t)(m0 >> 2) + ml4;            // spatial

    // stagger batch order per CTA to decorrelate chip-wide write windows
    const int cta   = mtile + 18 * c;         // 0..143
    const int start = (cta * 151) & 255;

    #pragma unroll 4
    for (int vv = 0; vv < 256; vv++) {
        int u = (vv + start) & 255;           // b = c + 8u
        base[(size_t)u * (8 * SLABSZ / 4)] = r0;
    }
}

// ---------------------------------------------------------------------------
extern "C" void kernel_launch(void* const* d_in, const int* in_sizes, int n_in,
                              void* d_out, int out_size) {
    const float* x     = (const float*)d_in[0];
    const float* fc_w  = (const float*)d_in[1];
    const float* fc_b  = (const float*)d_in[2];
    const float* oh_w  = (const float*)d_in[3];
    const float* oh_b  = (const float*)d_in[4];
    const float* ot_w  = (const float*)d_in[5];
    const float* ot_b  = (const float*)d_in[6];
    const float* all_w = (const float*)d_in[7];
    const float* all_b = (const float*)d_in[8];
    float* out = (float*)d_out;

    dim3 grid(18, 8);   // 144 CTAs, single wave, 1 CTA/SM, 32 warps/SM
    k_all<<<grid, THREADS>>>(x, fc_w, fc_b, oh_w, oh_b, ot_w, ot_b,
                             all_w, all_b, out);
}